// round 1
// baseline (speedup 1.0000x reference)
#include <cuda_runtime.h>

#define BSZ 2
#define TSEQ 2048
#define CDIM 1024
#define HN 16
#define DH 64

// Scratch (allocation-free rule: __device__ globals)
__device__ float g_qkv[(size_t)BSZ * TSEQ * 3 * CDIM];   // [B*T, 3C]
__device__ float g_y[(size_t)BSZ * TSEQ * CDIM];         // [B*T, C]

// ---------------------------------------------------------------------------
// SGEMM with fused bias: C[M,N] = A[M,K] @ B[K,N] + bias[N]
// 128x128 tile, BK=8, 256 threads, 8x8 per thread.
// ---------------------------------------------------------------------------
__global__ __launch_bounds__(256) void sgemm_bias(
    const float* __restrict__ A, const float* __restrict__ B,
    const float* __restrict__ bias, float* __restrict__ C,
    int M, int N, int K)
{
    __shared__ float As[8][128];   // transposed A tile: As[k][m]
    __shared__ float Bs[8][128];   // Bs[k][n]

    const int tid  = threadIdx.x;
    const int bm   = blockIdx.y;
    const int bn   = blockIdx.x;
    const int tRow = tid >> 4;     // 0..15
    const int tCol = tid & 15;     // 0..15

    // A tile load mapping: 128 rows x 8 cols, one float4 per thread
    const int rowA = tid >> 1;
    const int colA = (tid & 1) << 2;
    // B tile load mapping: 8 rows x 128 cols, one float4 per thread
    const int rowB = tid >> 5;
    const int colB = (tid & 31) << 2;

    const float* Aptr = A + (size_t)(bm * 128 + rowA) * K + colA;
    const float* Bptr = B + (size_t)rowB * N + bn * 128 + colB;

    float acc[8][8];
#pragma unroll
    for (int i = 0; i < 8; i++)
#pragma unroll
        for (int j = 0; j < 8; j++) acc[i][j] = 0.f;

    for (int k0 = 0; k0 < K; k0 += 8) {
        float4 a  = *(const float4*)(Aptr + k0);
        float4 b4 = *(const float4*)(Bptr + (size_t)k0 * N);
        As[colA + 0][rowA] = a.x;
        As[colA + 1][rowA] = a.y;
        As[colA + 2][rowA] = a.z;
        As[colA + 3][rowA] = a.w;
        *(float4*)&Bs[rowB][colB] = b4;
        __syncthreads();

#pragma unroll
        for (int kk = 0; kk < 8; kk++) {
            float ar[8], br[8];
#pragma unroll
            for (int i = 0; i < 4; i++) {
                ar[i]     = As[kk][tRow * 4 + i];
                ar[4 + i] = As[kk][64 + tRow * 4 + i];
                br[i]     = Bs[kk][tCol * 4 + i];
                br[4 + i] = Bs[kk][64 + tCol * 4 + i];
            }
#pragma unroll
            for (int i = 0; i < 8; i++)
#pragma unroll
                for (int j = 0; j < 8; j++)
                    acc[i][j] = fmaf(ar[i], br[j], acc[i][j]);
        }
        __syncthreads();
    }

    // Epilogue: add bias, float4 stores
#pragma unroll
    for (int i = 0; i < 8; i++) {
        int r = bm * 128 + ((i < 4) ? (tRow * 4 + i) : (64 + tRow * 4 + (i - 4)));
#pragma unroll
        for (int jh = 0; jh < 2; jh++) {
            int c = bn * 128 + jh * 64 + tCol * 4;
            float4 o;
            o.x = acc[i][jh * 4 + 0] + bias[c + 0];
            o.y = acc[i][jh * 4 + 1] + bias[c + 1];
            o.z = acc[i][jh * 4 + 2] + bias[c + 2];
            o.w = acc[i][jh * 4 + 3] + bias[c + 3];
            *(float4*)(C + (size_t)r * N + c) = o;
        }
    }
}

// ---------------------------------------------------------------------------
// Flash attention (fp32, causal). One CTA = 64 q-rows of one (b,h).
// Online softmax; S and PV GEMMs at 64x64x64 with 16x16 threads x (4x4).
// Shared layout (floats), all padded to 65 per row:
//   Qt[d][r], Kt[d][c], Vs[c][d], Pt[c][r]
// ---------------------------------------------------------------------------
#define SMPAD 65
#define TILE_F (64 * SMPAD)

__global__ __launch_bounds__(256) void attn_flash(
    const float* __restrict__ qkv, float* __restrict__ y)
{
    extern __shared__ float sm[];
    float* Qt = sm;
    float* Kt = sm + TILE_F;
    float* Vs = sm + 2 * TILE_F;
    float* Pt = sm + 3 * TILE_F;

    const int qb = blockIdx.x;   // q tile: rows qb*64..
    const int h  = blockIdx.y;
    const int b  = blockIdx.z;
    const int tid  = threadIdx.x;
    const int tRow = tid >> 4;   // 0..15
    const int tCol = tid & 15;   // 0..15

    const int ldr  = tid & 63;   // row within tile for loads
    const int ldc4 = tid >> 6;   // 0..3

    const size_t rs = 3 * CDIM;  // qkv row stride

    // Load Q tile transposed: Qt[d][r]
    {
        const float* qrow = qkv + ((size_t)(b * TSEQ + qb * 64 + ldr)) * rs + h * DH;
#pragma unroll
        for (int it = 0; it < 4; it++) {
            int d0 = (ldc4 + it * 4) * 4;
            float4 v = *(const float4*)(qrow + d0);
            Qt[(d0 + 0) * SMPAD + ldr] = v.x;
            Qt[(d0 + 1) * SMPAD + ldr] = v.y;
            Qt[(d0 + 2) * SMPAD + ldr] = v.z;
            Qt[(d0 + 3) * SMPAD + ldr] = v.w;
        }
    }

    float Oacc[4][4];
    float m[4], l[4];
#pragma unroll
    for (int i = 0; i < 4; i++) {
        m[i] = -1e30f;
        l[i] = 0.f;
#pragma unroll
        for (int j = 0; j < 4; j++) Oacc[i][j] = 0.f;
    }

    for (int kb = 0; kb <= qb; kb++) {
        __syncthreads();   // protect Kt/Vs/Pt from prior-iteration readers
        // Load K (transposed) and V (natural) tiles
        {
            const float* krow =
                qkv + ((size_t)(b * TSEQ + kb * 64 + ldr)) * rs + CDIM + h * DH;
#pragma unroll
            for (int it = 0; it < 4; it++) {
                int d0 = (ldc4 + it * 4) * 4;
                float4 kv = *(const float4*)(krow + d0);
                Kt[(d0 + 0) * SMPAD + ldr] = kv.x;
                Kt[(d0 + 1) * SMPAD + ldr] = kv.y;
                Kt[(d0 + 2) * SMPAD + ldr] = kv.z;
                Kt[(d0 + 3) * SMPAD + ldr] = kv.w;
                float4 vv = *(const float4*)(krow + CDIM + d0);
                Vs[ldr * SMPAD + d0 + 0] = vv.x;
                Vs[ldr * SMPAD + d0 + 1] = vv.y;
                Vs[ldr * SMPAD + d0 + 2] = vv.z;
                Vs[ldr * SMPAD + d0 + 3] = vv.w;
            }
        }
        __syncthreads();

        // S = Q @ K^T   (64x64x64)
        float s[4][4];
#pragma unroll
        for (int i = 0; i < 4; i++)
#pragma unroll
            for (int j = 0; j < 4; j++) s[i][j] = 0.f;

#pragma unroll 8
        for (int d = 0; d < 64; d++) {
            float qr[4], kc[4];
#pragma unroll
            for (int i = 0; i < 4; i++) qr[i] = Qt[d * SMPAD + tRow * 4 + i];
#pragma unroll
            for (int j = 0; j < 4; j++) kc[j] = Kt[d * SMPAD + tCol * 4 + j];
#pragma unroll
            for (int i = 0; i < 4; i++)
#pragma unroll
                for (int j = 0; j < 4; j++)
                    s[i][j] = fmaf(qr[i], kc[j], s[i][j]);
        }

        const float scale = 0.125f;   // 1/sqrt(64)
        if (kb == qb) {
#pragma unroll
            for (int i = 0; i < 4; i++)
#pragma unroll
                for (int j = 0; j < 4; j++) {
                    int r = tRow * 4 + i, c = tCol * 4 + j;
                    s[i][j] = (c <= r) ? s[i][j] * scale : -1e30f;
                }
        } else {
#pragma unroll
            for (int i = 0; i < 4; i++)
#pragma unroll
                for (int j = 0; j < 4; j++) s[i][j] *= scale;
        }

        // Online softmax update (rows split across 16 lanes sharing tRow)
#pragma unroll
        for (int i = 0; i < 4; i++) {
            float v = fmaxf(fmaxf(s[i][0], s[i][1]), fmaxf(s[i][2], s[i][3]));
#pragma unroll
            for (int off = 8; off; off >>= 1)
                v = fmaxf(v, __shfl_xor_sync(0xffffffffu, v, off));
            float mn = fmaxf(m[i], v);
            float alpha = __expf(m[i] - mn);
            m[i] = mn;

            float sum = 0.f;
#pragma unroll
            for (int j = 0; j < 4; j++) {
                float p = __expf(s[i][j] - mn);
                s[i][j] = p;
                sum += p;
            }
#pragma unroll
            for (int off = 8; off; off >>= 1)
                sum += __shfl_xor_sync(0xffffffffu, sum, off);
            l[i] = l[i] * alpha + sum;
#pragma unroll
            for (int j = 0; j < 4; j++) Oacc[i][j] *= alpha;
        }

        // Stage P transposed: Pt[c][r]
#pragma unroll
        for (int i = 0; i < 4; i++)
#pragma unroll
            for (int j = 0; j < 4; j++)
                Pt[(tCol * 4 + j) * SMPAD + tRow * 4 + i] = s[i][j];
        __syncthreads();

        // O += P @ V   (64x64x64)
#pragma unroll 8
        for (int c = 0; c < 64; c++) {
            float pr[4], vv[4];
#pragma unroll
            for (int i = 0; i < 4; i++) pr[i] = Pt[c * SMPAD + tRow * 4 + i];
#pragma unroll
            for (int j = 0; j < 4; j++) vv[j] = Vs[c * SMPAD + tCol * 4 + j];
#pragma unroll
            for (int i = 0; i < 4; i++)
#pragma unroll
                for (int j = 0; j < 4; j++)
                    Oacc[i][j] = fmaf(pr[i], vv[j], Oacc[i][j]);
        }
    }

    // Normalize and write y[b][t][h*64 + d]
#pragma unroll
    for (int i = 0; i < 4; i++) {
        float inv = 1.0f / l[i];
        size_t row = (size_t)(b * TSEQ + qb * 64 + tRow * 4 + i);
        float4 o;
        o.x = Oacc[i][0] * inv;
        o.y = Oacc[i][1] * inv;
        o.z = Oacc[i][2] * inv;
        o.w = Oacc[i][3] * inv;
        *(float4*)(y + row * CDIM + h * DH + tCol * 4) = o;
    }
}

// ---------------------------------------------------------------------------
extern "C" void kernel_launch(void* const* d_in, const int* in_sizes, int n_in,
                              void* d_out, int out_size)
{
    const float* x      = (const float*)d_in[0];
    const float* w_attn = (const float*)d_in[1];
    const float* b_attn = (const float*)d_in[2];
    const float* w_proj = (const float*)d_in[3];
    const float* b_proj = (const float*)d_in[4];
    float* out = (float*)d_out;

    float *qkv, *yb;
    cudaGetSymbolAddress((void**)&qkv, g_qkv);
    cudaGetSymbolAddress((void**)&yb, g_y);

    const int smem_attn = 4 * TILE_F * (int)sizeof(float);   // 66560 bytes
    cudaFuncSetAttribute(attn_flash, cudaFuncAttributeMaxDynamicSharedMemorySize,
                         smem_attn);

    const int M = BSZ * TSEQ;   // 4096

    // 1) qkv = x @ w_attn + b_attn     [4096, 3072]
    sgemm_bias<<<dim3((3 * CDIM) / 128, M / 128), 256>>>(
        x, w_attn, b_attn, qkv, M, 3 * CDIM, CDIM);

    // 2) flash attention -> y          [4096, 1024]
    attn_flash<<<dim3(TSEQ / 64, HN, BSZ), 256, smem_attn>>>(qkv, yb);

    // 3) out = y @ w_proj + b_proj     [4096, 1024]
    sgemm_bias<<<dim3(CDIM / 128, M / 128), 256>>>(
        yb, w_proj, b_proj, out, M, CDIM, CDIM);
}

// round 2
// speedup vs baseline: 1.3199x; 1.3199x over previous
#include <cuda_runtime.h>

#define BSZ 2
#define TSEQ 2048
#define CDIM 1024
#define HN 16
#define DH 64

// Scratch (allocation-free rule: __device__ globals)
__device__ float g_qkv[(size_t)BSZ * TSEQ * 3 * CDIM];   // [B*T, 3C]
__device__ float g_y[(size_t)BSZ * TSEQ * CDIM];         // [B*T, C]

// ---------------------------------------------------------------------------
// tf32 tensor-core GEMM with fused bias: C[M,N] = A[M,K] @ B[K,N] + bias[N]
// 128x128x32 CTA tile, 256 threads (8 warps), warp tile 64x32,
// mma.sync.m16n8k8 tf32. A smem row-major [128][36], B smem [32][136].
// ---------------------------------------------------------------------------
#define LDA 36
#define LDB 136

__device__ __forceinline__ unsigned f2tf32(float f) {
    unsigned r;
    asm("cvt.rna.tf32.f32 %0, %1;" : "=r"(r) : "f"(f));
    return r;
}

__device__ __forceinline__ void mma_tf32(float* c, const unsigned* a, const unsigned* b) {
    asm volatile(
        "mma.sync.aligned.m16n8k8.row.col.f32.tf32.tf32.f32 "
        "{%0,%1,%2,%3}, {%4,%5,%6,%7}, {%8,%9}, {%0,%1,%2,%3};"
        : "+f"(c[0]), "+f"(c[1]), "+f"(c[2]), "+f"(c[3])
        : "r"(a[0]), "r"(a[1]), "r"(a[2]), "r"(a[3]), "r"(b[0]), "r"(b[1]));
}

__global__ __launch_bounds__(256) void gemm_tf32_bias(
    const float* __restrict__ A, const float* __restrict__ B,
    const float* __restrict__ bias, float* __restrict__ C,
    int M, int N, int K)
{
    __shared__ unsigned sA[128 * LDA];   // [m][k], pad 36
    __shared__ unsigned sB[32 * LDB];    // [k][n], pad 136

    const int tid    = threadIdx.x;
    const int wid    = tid >> 5;
    const int lane   = tid & 31;
    const int g      = lane >> 2;        // groupID 0..7
    const int t      = lane & 3;         // threadInGroup 0..3
    const int warp_m = wid >> 2;         // 0..1
    const int warp_n = wid & 3;          // 0..3
    const int bm     = blockIdx.y;
    const int bn     = blockIdx.x;

    float acc[4][4][4];
#pragma unroll
    for (int i = 0; i < 4; i++)
#pragma unroll
        for (int j = 0; j < 4; j++)
#pragma unroll
            for (int v = 0; v < 4; v++) acc[i][j][v] = 0.f;

    const int wm = warp_m * 64;
    const int wn = warp_n * 32;

    for (int k0 = 0; k0 < K; k0 += 32) {
        // ---- load A tile: 128 rows x 32 cols ----
#pragma unroll
        for (int it = 0; it < 4; it++) {
            int gidx  = it * 256 + tid;
            int arow  = gidx >> 3;
            int acol  = (gidx & 7) << 2;
            float4 v = *(const float4*)(A + (size_t)(bm * 128 + arow) * K + k0 + acol);
            uint4 u;
            u.x = f2tf32(v.x); u.y = f2tf32(v.y);
            u.z = f2tf32(v.z); u.w = f2tf32(v.w);
            *(uint4*)&sA[arow * LDA + acol] = u;
        }
        // ---- load B tile: 32 rows x 128 cols ----
#pragma unroll
        for (int it = 0; it < 4; it++) {
            int gidx  = it * 256 + tid;
            int brow  = gidx >> 5;
            int bcol  = (gidx & 31) << 2;
            float4 v = *(const float4*)(B + (size_t)(k0 + brow) * N + bn * 128 + bcol);
            uint4 u;
            u.x = f2tf32(v.x); u.y = f2tf32(v.y);
            u.z = f2tf32(v.z); u.w = f2tf32(v.w);
            *(uint4*)&sB[brow * LDB + bcol] = u;
        }
        __syncthreads();

#pragma unroll
        for (int kk = 0; kk < 32; kk += 8) {
            unsigned af[4][4], bf[4][2];
#pragma unroll
            for (int mt = 0; mt < 4; mt++) {
                int m0 = wm + mt * 16;
                af[mt][0] = sA[(m0 + g) * LDA + kk + t];
                af[mt][1] = sA[(m0 + 8 + g) * LDA + kk + t];
                af[mt][2] = sA[(m0 + g) * LDA + kk + t + 4];
                af[mt][3] = sA[(m0 + 8 + g) * LDA + kk + t + 4];
            }
#pragma unroll
            for (int nt = 0; nt < 4; nt++) {
                int n0 = wn + nt * 8;
                bf[nt][0] = sB[(kk + t) * LDB + n0 + g];
                bf[nt][1] = sB[(kk + t + 4) * LDB + n0 + g];
            }
#pragma unroll
            for (int mt = 0; mt < 4; mt++)
#pragma unroll
                for (int nt = 0; nt < 4; nt++)
                    mma_tf32(acc[mt][nt], af[mt], bf[nt]);
        }
        __syncthreads();
    }

    // ---- epilogue: bias + store ----
#pragma unroll
    for (int nt = 0; nt < 4; nt++) {
        int col = bn * 128 + wn + nt * 8 + t * 2;
        float b0 = bias[col], b1 = bias[col + 1];
#pragma unroll
        for (int mt = 0; mt < 4; mt++) {
            int row0 = bm * 128 + wm + mt * 16 + g;
            float2 o0, o1;
            o0.x = acc[mt][nt][0] + b0;
            o0.y = acc[mt][nt][1] + b1;
            o1.x = acc[mt][nt][2] + b0;
            o1.y = acc[mt][nt][3] + b1;
            *(float2*)(C + (size_t)row0 * N + col)       = o0;
            *(float2*)(C + (size_t)(row0 + 8) * N + col) = o1;
        }
    }
}

// ---------------------------------------------------------------------------
// Flash attention (fp32, causal). One CTA = 64 q-rows of one (b,h).
// ---------------------------------------------------------------------------
#define SMPAD 65
#define TILE_F (64 * SMPAD)

__global__ __launch_bounds__(256) void attn_flash(
    const float* __restrict__ qkv, float* __restrict__ y)
{
    extern __shared__ float sm[];
    float* Qt = sm;
    float* Kt = sm + TILE_F;
    float* Vs = sm + 2 * TILE_F;
    float* Pt = sm + 3 * TILE_F;

    const int qb = blockIdx.x;
    const int h  = blockIdx.y;
    const int b  = blockIdx.z;
    const int tid  = threadIdx.x;
    const int tRow = tid >> 4;
    const int tCol = tid & 15;

    const int ldr  = tid & 63;
    const int ldc4 = tid >> 6;

    const size_t rs = 3 * CDIM;

    {
        const float* qrow = qkv + ((size_t)(b * TSEQ + qb * 64 + ldr)) * rs + h * DH;
#pragma unroll
        for (int it = 0; it < 4; it++) {
            int d0 = (ldc4 + it * 4) * 4;
            float4 v = *(const float4*)(qrow + d0);
            Qt[(d0 + 0) * SMPAD + ldr] = v.x;
            Qt[(d0 + 1) * SMPAD + ldr] = v.y;
            Qt[(d0 + 2) * SMPAD + ldr] = v.z;
            Qt[(d0 + 3) * SMPAD + ldr] = v.w;
        }
    }

    float Oacc[4][4];
    float m[4], l[4];
#pragma unroll
    for (int i = 0; i < 4; i++) {
        m[i] = -1e30f;
        l[i] = 0.f;
#pragma unroll
        for (int j = 0; j < 4; j++) Oacc[i][j] = 0.f;
    }

    for (int kb = 0; kb <= qb; kb++) {
        __syncthreads();
        {
            const float* krow =
                qkv + ((size_t)(b * TSEQ + kb * 64 + ldr)) * rs + CDIM + h * DH;
#pragma unroll
            for (int it = 0; it < 4; it++) {
                int d0 = (ldc4 + it * 4) * 4;
                float4 kv = *(const float4*)(krow + d0);
                Kt[(d0 + 0) * SMPAD + ldr] = kv.x;
                Kt[(d0 + 1) * SMPAD + ldr] = kv.y;
                Kt[(d0 + 2) * SMPAD + ldr] = kv.z;
                Kt[(d0 + 3) * SMPAD + ldr] = kv.w;
                float4 vv = *(const float4*)(krow + CDIM + d0);
                Vs[ldr * SMPAD + d0 + 0] = vv.x;
                Vs[ldr * SMPAD + d0 + 1] = vv.y;
                Vs[ldr * SMPAD + d0 + 2] = vv.z;
                Vs[ldr * SMPAD + d0 + 3] = vv.w;
            }
        }
        __syncthreads();

        float s[4][4];
#pragma unroll
        for (int i = 0; i < 4; i++)
#pragma unroll
            for (int j = 0; j < 4; j++) s[i][j] = 0.f;

#pragma unroll 8
        for (int d = 0; d < 64; d++) {
            float qr[4], kc[4];
#pragma unroll
            for (int i = 0; i < 4; i++) qr[i] = Qt[d * SMPAD + tRow * 4 + i];
#pragma unroll
            for (int j = 0; j < 4; j++) kc[j] = Kt[d * SMPAD + tCol * 4 + j];
#pragma unroll
            for (int i = 0; i < 4; i++)
#pragma unroll
                for (int j = 0; j < 4; j++)
                    s[i][j] = fmaf(qr[i], kc[j], s[i][j]);
        }

        const float scale = 0.125f;
        if (kb == qb) {
#pragma unroll
            for (int i = 0; i < 4; i++)
#pragma unroll
                for (int j = 0; j < 4; j++) {
                    int r = tRow * 4 + i, c = tCol * 4 + j;
                    s[i][j] = (c <= r) ? s[i][j] * scale : -1e30f;
                }
        } else {
#pragma unroll
            for (int i = 0; i < 4; i++)
#pragma unroll
                for (int j = 0; j < 4; j++) s[i][j] *= scale;
        }

#pragma unroll
        for (int i = 0; i < 4; i++) {
            float v = fmaxf(fmaxf(s[i][0], s[i][1]), fmaxf(s[i][2], s[i][3]));
#pragma unroll
            for (int off = 8; off; off >>= 1)
                v = fmaxf(v, __shfl_xor_sync(0xffffffffu, v, off));
            float mn = fmaxf(m[i], v);
            float alpha = __expf(m[i] - mn);
            m[i] = mn;

            float sum = 0.f;
#pragma unroll
            for (int j = 0; j < 4; j++) {
                float p = __expf(s[i][j] - mn);
                s[i][j] = p;
                sum += p;
            }
#pragma unroll
            for (int off = 8; off; off >>= 1)
                sum += __shfl_xor_sync(0xffffffffu, sum, off);
            l[i] = l[i] * alpha + sum;
#pragma unroll
            for (int j = 0; j < 4; j++) Oacc[i][j] *= alpha;
        }

#pragma unroll
        for (int i = 0; i < 4; i++)
#pragma unroll
            for (int j = 0; j < 4; j++)
                Pt[(tCol * 4 + j) * SMPAD + tRow * 4 + i] = s[i][j];
        __syncthreads();

#pragma unroll 8
        for (int c = 0; c < 64; c++) {
            float pr[4], vv[4];
#pragma unroll
            for (int i = 0; i < 4; i++) pr[i] = Pt[c * SMPAD + tRow * 4 + i];
#pragma unroll
            for (int j = 0; j < 4; j++) vv[j] = Vs[c * SMPAD + tCol * 4 + j];
#pragma unroll
            for (int i = 0; i < 4; i++)
#pragma unroll
                for (int j = 0; j < 4; j++)
                    Oacc[i][j] = fmaf(pr[i], vv[j], Oacc[i][j]);
        }
    }

#pragma unroll
    for (int i = 0; i < 4; i++) {
        float inv = 1.0f / l[i];
        size_t row = (size_t)(b * TSEQ + qb * 64 + tRow * 4 + i);
        float4 o;
        o.x = Oacc[i][0] * inv;
        o.y = Oacc[i][1] * inv;
        o.z = Oacc[i][2] * inv;
        o.w = Oacc[i][3] * inv;
        *(float4*)(y + row * CDIM + h * DH + tCol * 4) = o;
    }
}

// ---------------------------------------------------------------------------
extern "C" void kernel_launch(void* const* d_in, const int* in_sizes, int n_in,
                              void* d_out, int out_size)
{
    const float* x      = (const float*)d_in[0];
    const float* w_attn = (const float*)d_in[1];
    const float* b_attn = (const float*)d_in[2];
    const float* w_proj = (const float*)d_in[3];
    const float* b_proj = (const float*)d_in[4];
    float* out = (float*)d_out;

    float *qkv, *yb;
    cudaGetSymbolAddress((void**)&qkv, g_qkv);
    cudaGetSymbolAddress((void**)&yb, g_y);

    const int smem_attn = 4 * TILE_F * (int)sizeof(float);
    cudaFuncSetAttribute(attn_flash, cudaFuncAttributeMaxDynamicSharedMemorySize,
                         smem_attn);

    const int M = BSZ * TSEQ;   // 4096

    // 1) qkv = x @ w_attn + b_attn     [4096, 3072]
    gemm_tf32_bias<<<dim3((3 * CDIM) / 128, M / 128), 256>>>(
        x, w_attn, b_attn, qkv, M, 3 * CDIM, CDIM);

    // 2) flash attention -> y          [4096, 1024]
    attn_flash<<<dim3(TSEQ / 64, HN, BSZ), 256, smem_attn>>>(qkv, yb);

    // 3) out = y @ w_proj + b_proj     [4096, 1024]
    gemm_tf32_bias<<<dim3(CDIM / 128, M / 128), 256>>>(
        yb, w_proj, b_proj, out, M, CDIM, CDIM);
}

// round 3
// speedup vs baseline: 2.7685x; 2.0975x over previous
#include <cuda_runtime.h>

#define BSZ 2
#define TSEQ 2048
#define CDIM 1024
#define HN 16
#define DH 64

// Scratch (allocation-free rule: __device__ globals)
__device__ float g_qkv[(size_t)BSZ * TSEQ * 3 * CDIM];   // [B*T, 3C]
__device__ float g_y[(size_t)BSZ * TSEQ * CDIM];         // [B*T, C]

__device__ __forceinline__ unsigned f2tf32(float f) {
    unsigned r;
    asm("cvt.rna.tf32.f32 %0, %1;" : "=r"(r) : "f"(f));
    return r;
}

__device__ __forceinline__ void mma_tf32(float* c, const unsigned* a, const unsigned* b) {
    asm volatile(
        "mma.sync.aligned.m16n8k8.row.col.f32.tf32.tf32.f32 "
        "{%0,%1,%2,%3}, {%4,%5,%6,%7}, {%8,%9}, {%0,%1,%2,%3};"
        : "+f"(c[0]), "+f"(c[1]), "+f"(c[2]), "+f"(c[3])
        : "r"(a[0]), "r"(a[1]), "r"(a[2]), "r"(a[3]), "r"(b[0]), "r"(b[1]));
}

// ---------------------------------------------------------------------------
// tf32 tensor-core GEMM with fused bias: C[M,N] = A[M,K] @ B[K,N] + bias[N]
// ---------------------------------------------------------------------------
#define LDA 36
#define LDB 136

__global__ __launch_bounds__(256) void gemm_tf32_bias(
    const float* __restrict__ A, const float* __restrict__ B,
    const float* __restrict__ bias, float* __restrict__ C,
    int M, int N, int K)
{
    __shared__ unsigned sA[128 * LDA];   // [m][k], pad 36
    __shared__ unsigned sB[32 * LDB];    // [k][n], pad 136

    const int tid    = threadIdx.x;
    const int wid    = tid >> 5;
    const int lane   = tid & 31;
    const int g      = lane >> 2;
    const int t      = lane & 3;
    const int warp_m = wid >> 2;
    const int warp_n = wid & 3;
    const int bm     = blockIdx.y;
    const int bn     = blockIdx.x;

    float acc[4][4][4];
#pragma unroll
    for (int i = 0; i < 4; i++)
#pragma unroll
        for (int j = 0; j < 4; j++)
#pragma unroll
            for (int v = 0; v < 4; v++) acc[i][j][v] = 0.f;

    const int wm = warp_m * 64;
    const int wn = warp_n * 32;

    for (int k0 = 0; k0 < K; k0 += 32) {
#pragma unroll
        for (int it = 0; it < 4; it++) {
            int gidx  = it * 256 + tid;
            int arow  = gidx >> 3;
            int acol  = (gidx & 7) << 2;
            float4 v = *(const float4*)(A + (size_t)(bm * 128 + arow) * K + k0 + acol);
            uint4 u;
            u.x = f2tf32(v.x); u.y = f2tf32(v.y);
            u.z = f2tf32(v.z); u.w = f2tf32(v.w);
            *(uint4*)&sA[arow * LDA + acol] = u;
        }
#pragma unroll
        for (int it = 0; it < 4; it++) {
            int gidx  = it * 256 + tid;
            int brow  = gidx >> 5;
            int bcol  = (gidx & 31) << 2;
            float4 v = *(const float4*)(B + (size_t)(k0 + brow) * N + bn * 128 + bcol);
            uint4 u;
            u.x = f2tf32(v.x); u.y = f2tf32(v.y);
            u.z = f2tf32(v.z); u.w = f2tf32(v.w);
            *(uint4*)&sB[brow * LDB + bcol] = u;
        }
        __syncthreads();

#pragma unroll
        for (int kk = 0; kk < 32; kk += 8) {
            unsigned af[4][4], bf[4][2];
#pragma unroll
            for (int mt = 0; mt < 4; mt++) {
                int m0 = wm + mt * 16;
                af[mt][0] = sA[(m0 + g) * LDA + kk + t];
                af[mt][1] = sA[(m0 + 8 + g) * LDA + kk + t];
                af[mt][2] = sA[(m0 + g) * LDA + kk + t + 4];
                af[mt][3] = sA[(m0 + 8 + g) * LDA + kk + t + 4];
            }
#pragma unroll
            for (int nt = 0; nt < 4; nt++) {
                int n0 = wn + nt * 8;
                bf[nt][0] = sB[(kk + t) * LDB + n0 + g];
                bf[nt][1] = sB[(kk + t + 4) * LDB + n0 + g];
            }
#pragma unroll
            for (int mt = 0; mt < 4; mt++)
#pragma unroll
                for (int nt = 0; nt < 4; nt++)
                    mma_tf32(acc[mt][nt], af[mt], bf[nt]);
        }
        __syncthreads();
    }

#pragma unroll
    for (int nt = 0; nt < 4; nt++) {
        int col = bn * 128 + wn + nt * 8 + t * 2;
        float b0 = bias[col], b1 = bias[col + 1];
#pragma unroll
        for (int mt = 0; mt < 4; mt++) {
            int row0 = bm * 128 + wm + mt * 16 + g;
            float2 o0, o1;
            o0.x = acc[mt][nt][0] + b0;
            o0.y = acc[mt][nt][1] + b1;
            o1.x = acc[mt][nt][2] + b0;
            o1.y = acc[mt][nt][3] + b1;
            *(float2*)(C + (size_t)row0 * N + col)       = o0;
            *(float2*)(C + (size_t)(row0 + 8) * N + col) = o1;
        }
    }
}

// ---------------------------------------------------------------------------
// Flash attention with tf32 tensor-core MMA (causal).
// CTA = 128 q-rows of one (b,h); 8 warps, 16 q-rows per warp.
// S = Q@K^T via m16n8k8 (8 n-tiles), online softmax fp32, O += P@V via mma.
// Q smem region is reused as per-warp P staging (exact same rows).
// ---------------------------------------------------------------------------
#define LDQ 68
#define LDK 68
#define LDV 72
// floats: Q/P 128*68=8704, K 64*68=4352, V 64*72=4608 -> 17664 * 4B = 70656 B
#define ATTN_SMEM (128 * LDQ + 64 * LDK + 64 * LDV)

__global__ __launch_bounds__(256) void attn_flash_mma(
    const float* __restrict__ qkv, float* __restrict__ y)
{
    extern __shared__ unsigned smu[];
    unsigned* sQ = smu;                 // [128][LDQ] tf32; later reused as P
    unsigned* sK = sQ + 128 * LDQ;      // [64][LDK]
    unsigned* sV = sK + 64 * LDK;       // [64][LDV]

    const int qb   = blockIdx.x;
    const int h    = blockIdx.y;
    const int b    = blockIdx.z;
    const int tid  = threadIdx.x;
    const int wid  = tid >> 5;
    const int lane = tid & 31;
    const int g    = lane >> 2;
    const int t    = lane & 3;
    const int wq   = wid * 16;          // warp's q-row offset within the 128 tile

    const size_t rs = 3 * CDIM;
    const size_t baseQ = ((size_t)(b * TSEQ + qb * 128)) * rs + h * DH;

    // ---- load Q tile [128][64] -> tf32 smem ----
#pragma unroll
    for (int it = 0; it < 8; it++) {
        int idx = it * 256 + tid;
        int r = idx >> 4, c = (idx & 15) << 2;
        float4 v = *(const float4*)(qkv + baseQ + (size_t)r * rs + c);
        uint4 u;
        u.x = f2tf32(v.x); u.y = f2tf32(v.y);
        u.z = f2tf32(v.z); u.w = f2tf32(v.w);
        *(uint4*)&sQ[r * LDQ + c] = u;
    }
    __syncthreads();

    // ---- Q fragments into registers (reused for every k tile) ----
    unsigned qf[8][4];
#pragma unroll
    for (int kk = 0; kk < 8; kk++) {
        qf[kk][0] = sQ[(wq + g) * LDQ + kk * 8 + t];
        qf[kk][1] = sQ[(wq + 8 + g) * LDQ + kk * 8 + t];
        qf[kk][2] = sQ[(wq + g) * LDQ + kk * 8 + t + 4];
        qf[kk][3] = sQ[(wq + 8 + g) * LDQ + kk * 8 + t + 4];
    }

    unsigned* sP = sQ + wq * LDQ;       // per-warp P staging [16][LDQ]

    float o[8][4];
#pragma unroll
    for (int nt = 0; nt < 8; nt++)
#pragma unroll
        for (int j = 0; j < 4; j++) o[nt][j] = 0.f;
    float m0 = -1e30f, m1 = -1e30f, l0 = 0.f, l1 = 0.f;

    const int rowW = qb * 128 + wq;     // warp's min global q row
    const int r0g  = rowW + g;          // this thread's rows
    const int r1g  = rowW + 8 + g;
    const int nkb  = 2 * qb + 2;

    for (int kb = 0; kb < nkb; kb++) {
        __syncthreads();
        // ---- cooperative load K,V tiles [64][64] ----
        const size_t baseK = ((size_t)(b * TSEQ + kb * 64)) * rs + CDIM + h * DH;
#pragma unroll
        for (int it = 0; it < 4; it++) {
            int idx = it * 256 + tid;
            int r = idx >> 4, c = (idx & 15) << 2;
            float4 kv = *(const float4*)(qkv + baseK + (size_t)r * rs + c);
            uint4 uk;
            uk.x = f2tf32(kv.x); uk.y = f2tf32(kv.y);
            uk.z = f2tf32(kv.z); uk.w = f2tf32(kv.w);
            *(uint4*)&sK[r * LDK + c] = uk;
            float4 vv = *(const float4*)(qkv + baseK + CDIM + (size_t)r * rs + c);
            uint4 uv;
            uv.x = f2tf32(vv.x); uv.y = f2tf32(vv.y);
            uv.z = f2tf32(vv.z); uv.w = f2tf32(vv.w);
            *(uint4*)&sV[r * LDV + c] = uv;
        }
        __syncthreads();

        // fully masked for this warp? (all 16 rows above every key in tile)
        if (rowW + 15 < kb * 64) continue;

        // ---- S = Q @ K^T ----
        float s[8][4];
#pragma unroll
        for (int nt = 0; nt < 8; nt++)
#pragma unroll
            for (int j = 0; j < 4; j++) s[nt][j] = 0.f;

#pragma unroll
        for (int kk = 0; kk < 8; kk++) {
#pragma unroll
            for (int nt = 0; nt < 8; nt++) {
                unsigned bf[2];
                bf[0] = sK[(nt * 8 + g) * LDK + kk * 8 + t];
                bf[1] = sK[(nt * 8 + g) * LDK + kk * 8 + t + 4];
                mma_tf32(s[nt], qf[kk], bf);
            }
        }

        // ---- scale + causal mask ----
        const float scale = 0.125f;
        if (kb * 64 + 63 > rowW) {
#pragma unroll
            for (int nt = 0; nt < 8; nt++) {
                int c0 = kb * 64 + nt * 8 + 2 * t;
                s[nt][0] = (c0     <= r0g) ? s[nt][0] * scale : -1e30f;
                s[nt][1] = (c0 + 1 <= r0g) ? s[nt][1] * scale : -1e30f;
                s[nt][2] = (c0     <= r1g) ? s[nt][2] * scale : -1e30f;
                s[nt][3] = (c0 + 1 <= r1g) ? s[nt][3] * scale : -1e30f;
            }
        } else {
#pragma unroll
            for (int nt = 0; nt < 8; nt++)
#pragma unroll
                for (int j = 0; j < 4; j++) s[nt][j] *= scale;
        }

        // ---- online softmax (rows r0, r1; reduce across t-quad) ----
        float mx0 = -1e30f, mx1 = -1e30f;
#pragma unroll
        for (int nt = 0; nt < 8; nt++) {
            mx0 = fmaxf(mx0, fmaxf(s[nt][0], s[nt][1]));
            mx1 = fmaxf(mx1, fmaxf(s[nt][2], s[nt][3]));
        }
        mx0 = fmaxf(mx0, __shfl_xor_sync(0xffffffffu, mx0, 1));
        mx0 = fmaxf(mx0, __shfl_xor_sync(0xffffffffu, mx0, 2));
        mx1 = fmaxf(mx1, __shfl_xor_sync(0xffffffffu, mx1, 1));
        mx1 = fmaxf(mx1, __shfl_xor_sync(0xffffffffu, mx1, 2));

        float mn0 = fmaxf(m0, mx0), mn1 = fmaxf(m1, mx1);
        float a0 = __expf(m0 - mn0), a1 = __expf(m1 - mn1);
        m0 = mn0; m1 = mn1;

        float sum0 = 0.f, sum1 = 0.f;
#pragma unroll
        for (int nt = 0; nt < 8; nt++) {
            s[nt][0] = __expf(s[nt][0] - mn0);
            s[nt][1] = __expf(s[nt][1] - mn0);
            s[nt][2] = __expf(s[nt][2] - mn1);
            s[nt][3] = __expf(s[nt][3] - mn1);
            sum0 += s[nt][0] + s[nt][1];
            sum1 += s[nt][2] + s[nt][3];
        }
        sum0 += __shfl_xor_sync(0xffffffffu, sum0, 1);
        sum0 += __shfl_xor_sync(0xffffffffu, sum0, 2);
        sum1 += __shfl_xor_sync(0xffffffffu, sum1, 1);
        sum1 += __shfl_xor_sync(0xffffffffu, sum1, 2);
        l0 = l0 * a0 + sum0;
        l1 = l1 * a1 + sum1;

#pragma unroll
        for (int nt = 0; nt < 8; nt++) {
            o[nt][0] *= a0; o[nt][1] *= a0;
            o[nt][2] *= a1; o[nt][3] *= a1;
        }

        // ---- stage P (tf32) into per-warp smem buffer ----
        __syncwarp();
#pragma unroll
        for (int nt = 0; nt < 8; nt++) {
            int c0 = nt * 8 + 2 * t;
            uint2 u0, u1;
            u0.x = f2tf32(s[nt][0]); u0.y = f2tf32(s[nt][1]);
            u1.x = f2tf32(s[nt][2]); u1.y = f2tf32(s[nt][3]);
            *(uint2*)&sP[g * LDQ + c0]       = u0;
            *(uint2*)&sP[(8 + g) * LDQ + c0] = u1;
        }
        __syncwarp();

        // ---- O += P @ V ----
#pragma unroll
        for (int kk = 0; kk < 8; kk++) {
            unsigned pf[4];
            pf[0] = sP[g * LDQ + kk * 8 + t];
            pf[1] = sP[(8 + g) * LDQ + kk * 8 + t];
            pf[2] = sP[g * LDQ + kk * 8 + t + 4];
            pf[3] = sP[(8 + g) * LDQ + kk * 8 + t + 4];
#pragma unroll
            for (int nt = 0; nt < 8; nt++) {
                unsigned bf[2];
                bf[0] = sV[(kk * 8 + t) * LDV + nt * 8 + g];
                bf[1] = sV[(kk * 8 + t + 4) * LDV + nt * 8 + g];
                mma_tf32(o[nt], pf, bf);
            }
        }
        __syncwarp();
    }

    // ---- epilogue: normalize, write y ----
    float inv0 = 1.0f / l0, inv1 = 1.0f / l1;
    const size_t yr0 = ((size_t)(b * TSEQ) + r0g) * CDIM + h * DH;
    const size_t yr1 = ((size_t)(b * TSEQ) + r1g) * CDIM + h * DH;
#pragma unroll
    for (int nt = 0; nt < 8; nt++) {
        int c0 = nt * 8 + 2 * t;
        float2 v0, v1;
        v0.x = o[nt][0] * inv0; v0.y = o[nt][1] * inv0;
        v1.x = o[nt][2] * inv1; v1.y = o[nt][3] * inv1;
        *(float2*)(y + yr0 + c0) = v0;
        *(float2*)(y + yr1 + c0) = v1;
    }
}

// ---------------------------------------------------------------------------
extern "C" void kernel_launch(void* const* d_in, const int* in_sizes, int n_in,
                              void* d_out, int out_size)
{
    const float* x      = (const float*)d_in[0];
    const float* w_attn = (const float*)d_in[1];
    const float* b_attn = (const float*)d_in[2];
    const float* w_proj = (const float*)d_in[3];
    const float* b_proj = (const float*)d_in[4];
    float* out = (float*)d_out;

    float *qkv, *yb;
    cudaGetSymbolAddress((void**)&qkv, g_qkv);
    cudaGetSymbolAddress((void**)&yb, g_y);

    const int smem_attn = ATTN_SMEM * (int)sizeof(unsigned);   // 70656 B
    cudaFuncSetAttribute(attn_flash_mma, cudaFuncAttributeMaxDynamicSharedMemorySize,
                         smem_attn);

    const int M = BSZ * TSEQ;   // 4096

    // 1) qkv = x @ w_attn + b_attn     [4096, 3072]
    gemm_tf32_bias<<<dim3((3 * CDIM) / 128, M / 128), 256>>>(
        x, w_attn, b_attn, qkv, M, 3 * CDIM, CDIM);

    // 2) flash attention (tensor cores) -> y   [4096, 1024]
    attn_flash_mma<<<dim3(TSEQ / 128, HN, BSZ), 256, smem_attn>>>(qkv, yb);

    // 3) out = y @ w_proj + b_proj     [4096, 1024]
    gemm_tf32_bias<<<dim3(CDIM / 128, M / 128), 256>>>(
        yb, w_proj, b_proj, out, M, CDIM, CDIM);
}

// round 4
// speedup vs baseline: 3.4505x; 1.2464x over previous
#include <cuda_runtime.h>

#define BSZ 2
#define TSEQ 2048
#define CDIM 1024
#define HN 16
#define DH 64

// Scratch (allocation-free rule: __device__ globals)
__device__ float g_qkv[(size_t)BSZ * TSEQ * 3 * CDIM];   // [B*T, 3C]
__device__ float g_y[(size_t)BSZ * TSEQ * CDIM];         // [B*T, C]

__device__ __forceinline__ unsigned f2tf32(float f) {
    unsigned r;
    asm("cvt.rna.tf32.f32 %0, %1;" : "=r"(r) : "f"(f));
    return r;
}

__device__ __forceinline__ void mma_tf32(float* c, const unsigned* a, const unsigned* b) {
    asm volatile(
        "mma.sync.aligned.m16n8k8.row.col.f32.tf32.tf32.f32 "
        "{%0,%1,%2,%3}, {%4,%5,%6,%7}, {%8,%9}, {%0,%1,%2,%3};"
        : "+f"(c[0]), "+f"(c[1]), "+f"(c[2]), "+f"(c[3])
        : "r"(a[0]), "r"(a[1]), "r"(a[2]), "r"(a[3]), "r"(b[0]), "r"(b[1]));
}

__device__ __forceinline__ void cp_async16(void* smem, const void* gmem) {
    unsigned saddr = (unsigned)__cvta_generic_to_shared(smem);
    asm volatile("cp.async.cg.shared.global [%0], [%1], 16;" :: "r"(saddr), "l"(gmem));
}
__device__ __forceinline__ void cp_commit() {
    asm volatile("cp.async.commit_group;");
}
__device__ __forceinline__ void cp_wait1() {
    asm volatile("cp.async.wait_group 1;");
}
__device__ __forceinline__ void cp_wait0() {
    asm volatile("cp.async.wait_group 0;");
}

// ---------------------------------------------------------------------------
// tf32 tensor-core GEMM, cp.async double-buffered.
// C[M,N] = A[M,K] @ B[K,N] + bias[N]. 128x128x32 tile, 256 thr, warp 64x32.
// smem holds raw fp32; cvt->tf32 at fragment load.
// ---------------------------------------------------------------------------
#define LDA 36
#define LDB 136
#define STG_A (128 * LDA)
#define STG_B (32 * LDB)
#define GEMM_SMEM (2 * (STG_A + STG_B))   // floats

__global__ __launch_bounds__(256, 2) void gemm_tf32_bias(
    const float* __restrict__ A, const float* __restrict__ B,
    const float* __restrict__ bias, float* __restrict__ C,
    int M, int N, int K)
{
    extern __shared__ float sg[];
    float* sA = sg;                    // [2][128][LDA]
    float* sB = sg + 2 * STG_A;        // [2][32][LDB]

    const int tid    = threadIdx.x;
    const int wid    = tid >> 5;
    const int lane   = tid & 31;
    const int g      = lane >> 2;
    const int t      = lane & 3;
    const int warp_m = wid >> 2;
    const int warp_n = wid & 3;
    const int bm     = blockIdx.y;
    const int bn     = blockIdx.x;

    // load mappings
    const int arow = tid >> 1;               // with 4 iters: rows tid>>3-style below
    (void)arow;

    float acc[4][4][4];
#pragma unroll
    for (int i = 0; i < 4; i++)
#pragma unroll
        for (int j = 0; j < 4; j++)
#pragma unroll
            for (int v = 0; v < 4; v++) acc[i][j][v] = 0.f;

    const int wm = warp_m * 64;
    const int wn = warp_n * 32;
    const int NK = K >> 5;

    // tile prefetch: A 128x32 (1024 chunks), B 32x128 (1024 chunks)
    auto load_tiles = [&](int buf, int k0) {
        float* dA = sA + buf * STG_A;
        float* dB = sB + buf * STG_B;
#pragma unroll
        for (int it = 0; it < 4; it++) {
            int gidx = it * 256 + tid;
            int r = gidx >> 3, c = (gidx & 7) << 2;
            cp_async16(&dA[r * LDA + c],
                       A + (size_t)(bm * 128 + r) * K + k0 + c);
        }
#pragma unroll
        for (int it = 0; it < 4; it++) {
            int gidx = it * 256 + tid;
            int r = gidx >> 5, c = (gidx & 31) << 2;
            cp_async16(&dB[r * LDB + c],
                       B + (size_t)(k0 + r) * N + bn * 128 + c);
        }
        cp_commit();
    };

    load_tiles(0, 0);

    for (int i = 0; i < NK; i++) {
        if (i + 1 < NK) {
            load_tiles((i + 1) & 1, (i + 1) << 5);
            cp_wait1();
        } else {
            cp_wait0();
        }
        __syncthreads();

        const float* cA = sA + (i & 1) * STG_A;
        const float* cB = sB + (i & 1) * STG_B;

#pragma unroll
        for (int kk = 0; kk < 32; kk += 8) {
            unsigned af[4][4], bf[4][2];
#pragma unroll
            for (int mt = 0; mt < 4; mt++) {
                int m0 = wm + mt * 16;
                af[mt][0] = f2tf32(cA[(m0 + g) * LDA + kk + t]);
                af[mt][1] = f2tf32(cA[(m0 + 8 + g) * LDA + kk + t]);
                af[mt][2] = f2tf32(cA[(m0 + g) * LDA + kk + t + 4]);
                af[mt][3] = f2tf32(cA[(m0 + 8 + g) * LDA + kk + t + 4]);
            }
#pragma unroll
            for (int nt = 0; nt < 4; nt++) {
                int n0 = wn + nt * 8;
                bf[nt][0] = f2tf32(cB[(kk + t) * LDB + n0 + g]);
                bf[nt][1] = f2tf32(cB[(kk + t + 4) * LDB + n0 + g]);
            }
#pragma unroll
            for (int mt = 0; mt < 4; mt++)
#pragma unroll
                for (int nt = 0; nt < 4; nt++)
                    mma_tf32(acc[mt][nt], af[mt], bf[nt]);
        }
        __syncthreads();
    }

    // ---- epilogue: bias + store ----
#pragma unroll
    for (int nt = 0; nt < 4; nt++) {
        int col = bn * 128 + wn + nt * 8 + t * 2;
        float b0 = bias[col], b1 = bias[col + 1];
#pragma unroll
        for (int mt = 0; mt < 4; mt++) {
            int row0 = bm * 128 + wm + mt * 16 + g;
            float2 o0, o1;
            o0.x = acc[mt][nt][0] + b0;
            o0.y = acc[mt][nt][1] + b1;
            o1.x = acc[mt][nt][2] + b0;
            o1.y = acc[mt][nt][3] + b1;
            *(float2*)(C + (size_t)row0 * N + col)       = o0;
            *(float2*)(C + (size_t)(row0 + 8) * N + col) = o1;
        }
    }
}

// ---------------------------------------------------------------------------
// Flash attention, tf32 MMA, cp.async double-buffered K/V (causal).
// CTA = 128 q-rows of one (b,h); 8 warps, 16 q-rows each.
// ---------------------------------------------------------------------------
#define LDQ 68
#define LDK 68
#define LDV 72
// u32 units: Q 128*68 + K 2*64*68 + V 2*64*72
#define ATTN_SMEM (128 * LDQ + 2 * 64 * LDK + 2 * 64 * LDV)

__global__ __launch_bounds__(256) void attn_flash_mma(
    const float* __restrict__ qkv, float* __restrict__ y)
{
    extern __shared__ unsigned smu[];
    unsigned* sQ = smu;                          // [128][LDQ] tf32; reused as P
    float* sK = (float*)(smu + 128 * LDQ);       // [2][64][LDK] raw f32
    float* sV = sK + 2 * 64 * LDK;               // [2][64][LDV] raw f32

    const int qb   = blockIdx.x;
    const int h    = blockIdx.y;
    const int b    = blockIdx.z;
    const int tid  = threadIdx.x;
    const int wid  = tid >> 5;
    const int lane = tid & 31;
    const int g    = lane >> 2;
    const int t    = lane & 3;
    const int wq   = wid * 16;

    const size_t rs = 3 * CDIM;
    const size_t baseQ = ((size_t)(b * TSEQ + qb * 128)) * rs + h * DH;

    // ---- load Q tile [128][64] -> tf32 smem ----
#pragma unroll
    for (int it = 0; it < 8; it++) {
        int idx = it * 256 + tid;
        int r = idx >> 4, c = (idx & 15) << 2;
        float4 v = *(const float4*)(qkv + baseQ + (size_t)r * rs + c);
        uint4 u;
        u.x = f2tf32(v.x); u.y = f2tf32(v.y);
        u.z = f2tf32(v.z); u.w = f2tf32(v.w);
        *(uint4*)&sQ[r * LDQ + c] = u;
    }

    const int nkb = 2 * qb + 2;

    auto load_kv = [&](int buf, int kb) {
        const size_t baseK = ((size_t)(b * TSEQ + kb * 64)) * rs + CDIM + h * DH;
        float* dK = sK + buf * 64 * LDK;
        float* dV = sV + buf * 64 * LDV;
#pragma unroll
        for (int it = 0; it < 4; it++) {
            int idx = it * 256 + tid;
            int r = idx >> 4, c = (idx & 15) << 2;
            cp_async16(&dK[r * LDK + c], qkv + baseK + (size_t)r * rs + c);
            cp_async16(&dV[r * LDV + c], qkv + baseK + CDIM + (size_t)r * rs + c);
        }
        cp_commit();
    };

    load_kv(0, 0);
    __syncthreads();   // sQ visible to all (fragments read below)

    // ---- Q fragments into registers ----
    unsigned qf[8][4];
#pragma unroll
    for (int kk = 0; kk < 8; kk++) {
        qf[kk][0] = sQ[(wq + g) * LDQ + kk * 8 + t];
        qf[kk][1] = sQ[(wq + 8 + g) * LDQ + kk * 8 + t];
        qf[kk][2] = sQ[(wq + g) * LDQ + kk * 8 + t + 4];
        qf[kk][3] = sQ[(wq + 8 + g) * LDQ + kk * 8 + t + 4];
    }

    unsigned* sP = sQ + wq * LDQ;   // per-warp P staging [16][LDQ]

    float o[8][4];
#pragma unroll
    for (int nt = 0; nt < 8; nt++)
#pragma unroll
        for (int j = 0; j < 4; j++) o[nt][j] = 0.f;
    float m0 = -1e30f, m1 = -1e30f, l0 = 0.f, l1 = 0.f;

    const int rowW = qb * 128 + wq;
    const int r0g  = rowW + g;
    const int r1g  = rowW + 8 + g;

    for (int kb = 0; kb < nkb; kb++) {
        if (kb + 1 < nkb) {
            load_kv((kb + 1) & 1, kb + 1);
            cp_wait1();
        } else {
            cp_wait0();
        }
        __syncthreads();

        const bool active = (rowW + 15 >= kb * 64);
        if (active) {
            const float* cK = sK + (kb & 1) * 64 * LDK;
            const float* cV = sV + (kb & 1) * 64 * LDV;

            // ---- S = Q @ K^T ----
            float s[8][4];
#pragma unroll
            for (int nt = 0; nt < 8; nt++)
#pragma unroll
                for (int j = 0; j < 4; j++) s[nt][j] = 0.f;

#pragma unroll
            for (int kk = 0; kk < 8; kk++) {
#pragma unroll
                for (int nt = 0; nt < 8; nt++) {
                    unsigned bf[2];
                    bf[0] = f2tf32(cK[(nt * 8 + g) * LDK + kk * 8 + t]);
                    bf[1] = f2tf32(cK[(nt * 8 + g) * LDK + kk * 8 + t + 4]);
                    mma_tf32(s[nt], qf[kk], bf);
                }
            }

            // ---- scale + causal mask ----
            const float scale = 0.125f;
            if (kb * 64 + 63 > rowW) {
#pragma unroll
                for (int nt = 0; nt < 8; nt++) {
                    int c0 = kb * 64 + nt * 8 + 2 * t;
                    s[nt][0] = (c0     <= r0g) ? s[nt][0] * scale : -1e30f;
                    s[nt][1] = (c0 + 1 <= r0g) ? s[nt][1] * scale : -1e30f;
                    s[nt][2] = (c0     <= r1g) ? s[nt][2] * scale : -1e30f;
                    s[nt][3] = (c0 + 1 <= r1g) ? s[nt][3] * scale : -1e30f;
                }
            } else {
#pragma unroll
                for (int nt = 0; nt < 8; nt++)
#pragma unroll
                    for (int j = 0; j < 4; j++) s[nt][j] *= scale;
            }

            // ---- online softmax ----
            float mx0 = -1e30f, mx1 = -1e30f;
#pragma unroll
            for (int nt = 0; nt < 8; nt++) {
                mx0 = fmaxf(mx0, fmaxf(s[nt][0], s[nt][1]));
                mx1 = fmaxf(mx1, fmaxf(s[nt][2], s[nt][3]));
            }
            mx0 = fmaxf(mx0, __shfl_xor_sync(0xffffffffu, mx0, 1));
            mx0 = fmaxf(mx0, __shfl_xor_sync(0xffffffffu, mx0, 2));
            mx1 = fmaxf(mx1, __shfl_xor_sync(0xffffffffu, mx1, 1));
            mx1 = fmaxf(mx1, __shfl_xor_sync(0xffffffffu, mx1, 2));

            float mn0 = fmaxf(m0, mx0), mn1 = fmaxf(m1, mx1);
            float a0 = __expf(m0 - mn0), a1 = __expf(m1 - mn1);
            m0 = mn0; m1 = mn1;

            float sum0 = 0.f, sum1 = 0.f;
#pragma unroll
            for (int nt = 0; nt < 8; nt++) {
                s[nt][0] = __expf(s[nt][0] - mn0);
                s[nt][1] = __expf(s[nt][1] - mn0);
                s[nt][2] = __expf(s[nt][2] - mn1);
                s[nt][3] = __expf(s[nt][3] - mn1);
                sum0 += s[nt][0] + s[nt][1];
                sum1 += s[nt][2] + s[nt][3];
            }
            sum0 += __shfl_xor_sync(0xffffffffu, sum0, 1);
            sum0 += __shfl_xor_sync(0xffffffffu, sum0, 2);
            sum1 += __shfl_xor_sync(0xffffffffu, sum1, 1);
            sum1 += __shfl_xor_sync(0xffffffffu, sum1, 2);
            l0 = l0 * a0 + sum0;
            l1 = l1 * a1 + sum1;

#pragma unroll
            for (int nt = 0; nt < 8; nt++) {
                o[nt][0] *= a0; o[nt][1] *= a0;
                o[nt][2] *= a1; o[nt][3] *= a1;
            }

            // ---- stage P (tf32) into per-warp smem ----
            __syncwarp();
#pragma unroll
            for (int nt = 0; nt < 8; nt++) {
                int c0 = nt * 8 + 2 * t;
                uint2 u0, u1;
                u0.x = f2tf32(s[nt][0]); u0.y = f2tf32(s[nt][1]);
                u1.x = f2tf32(s[nt][2]); u1.y = f2tf32(s[nt][3]);
                *(uint2*)&sP[g * LDQ + c0]       = u0;
                *(uint2*)&sP[(8 + g) * LDQ + c0] = u1;
            }
            __syncwarp();

            // ---- O += P @ V ----
#pragma unroll
            for (int kk = 0; kk < 8; kk++) {
                unsigned pf[4];
                pf[0] = sP[g * LDQ + kk * 8 + t];
                pf[1] = sP[(8 + g) * LDQ + kk * 8 + t];
                pf[2] = sP[g * LDQ + kk * 8 + t + 4];
                pf[3] = sP[(8 + g) * LDQ + kk * 8 + t + 4];
#pragma unroll
                for (int nt = 0; nt < 8; nt++) {
                    unsigned bf[2];
                    bf[0] = f2tf32(cV[(kk * 8 + t) * LDV + nt * 8 + g]);
                    bf[1] = f2tf32(cV[(kk * 8 + t + 4) * LDV + nt * 8 + g]);
                    mma_tf32(o[nt], pf, bf);
                }
            }
        }
        __syncthreads();   // protect K/V buffer reuse at next prefetch
    }

    // ---- epilogue ----
    float inv0 = 1.0f / l0, inv1 = 1.0f / l1;
    const size_t yr0 = ((size_t)(b * TSEQ) + r0g) * CDIM + h * DH;
    const size_t yr1 = ((size_t)(b * TSEQ) + r1g) * CDIM + h * DH;
#pragma unroll
    for (int nt = 0; nt < 8; nt++) {
        int c0 = nt * 8 + 2 * t;
        float2 v0, v1;
        v0.x = o[nt][0] * inv0; v0.y = o[nt][1] * inv0;
        v1.x = o[nt][2] * inv1; v1.y = o[nt][3] * inv1;
        *(float2*)(y + yr0 + c0) = v0;
        *(float2*)(y + yr1 + c0) = v1;
    }
}

// ---------------------------------------------------------------------------
extern "C" void kernel_launch(void* const* d_in, const int* in_sizes, int n_in,
                              void* d_out, int out_size)
{
    const float* x      = (const float*)d_in[0];
    const float* w_attn = (const float*)d_in[1];
    const float* b_attn = (const float*)d_in[2];
    const float* w_proj = (const float*)d_in[3];
    const float* b_proj = (const float*)d_in[4];
    float* out = (float*)d_out;

    float *qkv, *yb;
    cudaGetSymbolAddress((void**)&qkv, g_qkv);
    cudaGetSymbolAddress((void**)&yb, g_y);

    const int smem_gemm = GEMM_SMEM * (int)sizeof(float);      // 71680 B
    const int smem_attn = ATTN_SMEM * (int)sizeof(unsigned);   // 106496 B
    cudaFuncSetAttribute(gemm_tf32_bias, cudaFuncAttributeMaxDynamicSharedMemorySize,
                         smem_gemm);
    cudaFuncSetAttribute(attn_flash_mma, cudaFuncAttributeMaxDynamicSharedMemorySize,
                         smem_attn);

    const int M = BSZ * TSEQ;   // 4096

    // 1) qkv = x @ w_attn + b_attn     [4096, 3072]
    gemm_tf32_bias<<<dim3((3 * CDIM) / 128, M / 128), 256, smem_gemm>>>(
        x, w_attn, b_attn, qkv, M, 3 * CDIM, CDIM);

    // 2) flash attention (tensor cores) -> y   [4096, 1024]
    attn_flash_mma<<<dim3(TSEQ / 128, HN, BSZ), 256, smem_attn>>>(qkv, yb);

    // 3) out = y @ w_proj + b_proj     [4096, 1024]
    gemm_tf32_bias<<<dim3(CDIM / 128, M / 128), 256, smem_gemm>>>(
        yb, w_proj, b_proj, out, M, CDIM, CDIM);
}

// round 5
// speedup vs baseline: 3.9602x; 1.1477x over previous
#include <cuda_runtime.h>

#define BSZ 2
#define TSEQ 2048
#define CDIM 1024
#define HN 16
#define DH 64

// Scratch (allocation-free rule: __device__ globals). All tf32 bit-patterns.
__device__ unsigned g_x32[(size_t)BSZ * TSEQ * CDIM];        // x as tf32
__device__ unsigned g_wa32[(size_t)CDIM * 3 * CDIM];         // w_attn as tf32
__device__ unsigned g_wp32[(size_t)CDIM * CDIM];             // w_proj as tf32
__device__ unsigned g_qkv[(size_t)BSZ * TSEQ * 3 * CDIM];    // qkv as tf32
__device__ unsigned g_y[(size_t)BSZ * TSEQ * CDIM];          // y as tf32

__device__ __forceinline__ unsigned f2tf32(float f) {
    unsigned r;
    asm("cvt.rna.tf32.f32 %0, %1;" : "=r"(r) : "f"(f));
    return r;
}

__device__ __forceinline__ void mma_tf32(float* c, const unsigned* a, const unsigned* b) {
    asm volatile(
        "mma.sync.aligned.m16n8k8.row.col.f32.tf32.tf32.f32 "
        "{%0,%1,%2,%3}, {%4,%5,%6,%7}, {%8,%9}, {%0,%1,%2,%3};"
        : "+f"(c[0]), "+f"(c[1]), "+f"(c[2]), "+f"(c[3])
        : "r"(a[0]), "r"(a[1]), "r"(a[2]), "r"(a[3]), "r"(b[0]), "r"(b[1]));
}

__device__ __forceinline__ void cp_async16(void* smem, const void* gmem) {
    unsigned saddr = (unsigned)__cvta_generic_to_shared(smem);
    asm volatile("cp.async.cg.shared.global [%0], [%1], 16;" :: "r"(saddr), "l"(gmem));
}
__device__ __forceinline__ void cp_commit() { asm volatile("cp.async.commit_group;"); }
__device__ __forceinline__ void cp_wait1()  { asm volatile("cp.async.wait_group 1;"); }
__device__ __forceinline__ void cp_wait0()  { asm volatile("cp.async.wait_group 0;"); }

__device__ __forceinline__ void ldm_x4(unsigned* r, const void* smem) {
    unsigned saddr = (unsigned)__cvta_generic_to_shared(smem);
    asm volatile("ldmatrix.sync.aligned.m8n8.x4.shared.b16 {%0,%1,%2,%3}, [%4];"
        : "=r"(r[0]), "=r"(r[1]), "=r"(r[2]), "=r"(r[3]) : "r"(saddr));
}
__device__ __forceinline__ void ldm_x2(unsigned* r, const void* smem) {
    unsigned saddr = (unsigned)__cvta_generic_to_shared(smem);
    asm volatile("ldmatrix.sync.aligned.m8n8.x2.shared.b16 {%0,%1}, [%2];"
        : "=r"(r[0]), "=r"(r[1]) : "r"(saddr));
}

// ---------------------------------------------------------------------------
// fp32 -> tf32 pre-convert (vectorized)
// ---------------------------------------------------------------------------
__global__ __launch_bounds__(256) void cvt_tf32(
    const float* __restrict__ in, unsigned* __restrict__ out, int n4)
{
    int i = blockIdx.x * 256 + threadIdx.x;
    if (i < n4) {
        float4 v = *(const float4*)(in + (size_t)i * 4);
        uint4 u;
        u.x = f2tf32(v.x); u.y = f2tf32(v.y);
        u.z = f2tf32(v.z); u.w = f2tf32(v.w);
        *(uint4*)(out + (size_t)i * 4) = u;
    }
}

// ---------------------------------------------------------------------------
// tf32 tensor-core GEMM, cp.async double-buffered, ldmatrix A-frags.
// C[M,N] = A[M,K] @ B[K,N] + bias[N]; A,B are tf32 bits in global.
// OUT_TF32: write C as tf32 bits (for qkv) vs fp32 (final output).
// ---------------------------------------------------------------------------
#define LDA 36
#define LDB 136
#define STG_A (128 * LDA)
#define STG_B (32 * LDB)
#define GEMM_SMEM (2 * (STG_A + STG_B))

template <bool OUT_TF32>
__global__ __launch_bounds__(256, 2) void gemm_tf32_bias(
    const unsigned* __restrict__ A, const unsigned* __restrict__ B,
    const float* __restrict__ bias, void* __restrict__ Cv,
    int M, int N, int K)
{
    extern __shared__ unsigned sg[];
    unsigned* sA = sg;
    unsigned* sB = sg + 2 * STG_A;

    const int tid    = threadIdx.x;
    const int wid    = tid >> 5;
    const int lane   = tid & 31;
    const int g      = lane >> 2;
    const int t      = lane & 3;
    const int warp_m = wid >> 2;
    const int warp_n = wid & 3;
    const int bm     = blockIdx.y;
    const int bn     = blockIdx.x;

    float acc[4][4][4];
#pragma unroll
    for (int i = 0; i < 4; i++)
#pragma unroll
        for (int j = 0; j < 4; j++)
#pragma unroll
            for (int v = 0; v < 4; v++) acc[i][j][v] = 0.f;

    const int wm = warp_m * 64;
    const int wn = warp_n * 32;
    const int NK = K >> 5;

    // ldmatrix per-lane address components for A fragments
    const int rowL   = lane & 15;          // row within 16-row frag
    const int colOff = (lane >> 4) << 2;   // 0 or 4

    auto load_tiles = [&](int buf, int k0) {
        unsigned* dA = sA + buf * STG_A;
        unsigned* dB = sB + buf * STG_B;
#pragma unroll
        for (int it = 0; it < 4; it++) {
            int gidx = it * 256 + tid;
            int r = gidx >> 3, c = (gidx & 7) << 2;
            cp_async16(&dA[r * LDA + c], A + (size_t)(bm * 128 + r) * K + k0 + c);
        }
#pragma unroll
        for (int it = 0; it < 4; it++) {
            int gidx = it * 256 + tid;
            int r = gidx >> 5, c = (gidx & 31) << 2;
            cp_async16(&dB[r * LDB + c], B + (size_t)(k0 + r) * N + bn * 128 + c);
        }
        cp_commit();
    };

    load_tiles(0, 0);

    for (int i = 0; i < NK; i++) {
        if (i + 1 < NK) {
            load_tiles((i + 1) & 1, (i + 1) << 5);
            cp_wait1();
        } else {
            cp_wait0();
        }
        __syncthreads();

        const unsigned* cA = sA + (i & 1) * STG_A;
        const unsigned* cB = sB + (i & 1) * STG_B;

#pragma unroll
        for (int kk = 0; kk < 32; kk += 8) {
            unsigned af[4][4], bf[4][2];
#pragma unroll
            for (int mt = 0; mt < 4; mt++)
                ldm_x4(af[mt], &cA[(wm + mt * 16 + rowL) * LDA + kk + colOff]);
#pragma unroll
            for (int nt = 0; nt < 4; nt++) {
                int n0 = wn + nt * 8;
                bf[nt][0] = cB[(kk + t) * LDB + n0 + g];
                bf[nt][1] = cB[(kk + t + 4) * LDB + n0 + g];
            }
#pragma unroll
            for (int mt = 0; mt < 4; mt++)
#pragma unroll
                for (int nt = 0; nt < 4; nt++)
                    mma_tf32(acc[mt][nt], af[mt], bf[nt]);
        }
        __syncthreads();
    }

    // ---- epilogue: bias + store ----
#pragma unroll
    for (int nt = 0; nt < 4; nt++) {
        int col = bn * 128 + wn + nt * 8 + t * 2;
        float b0 = bias[col], b1 = bias[col + 1];
#pragma unroll
        for (int mt = 0; mt < 4; mt++) {
            int row0 = bm * 128 + wm + mt * 16 + g;
            float v00 = acc[mt][nt][0] + b0, v01 = acc[mt][nt][1] + b1;
            float v10 = acc[mt][nt][2] + b0, v11 = acc[mt][nt][3] + b1;
            if (OUT_TF32) {
                unsigned* C = (unsigned*)Cv;
                uint2 u0, u1;
                u0.x = f2tf32(v00); u0.y = f2tf32(v01);
                u1.x = f2tf32(v10); u1.y = f2tf32(v11);
                *(uint2*)(C + (size_t)row0 * N + col)       = u0;
                *(uint2*)(C + (size_t)(row0 + 8) * N + col) = u1;
            } else {
                float* C = (float*)Cv;
                float2 o0, o1;
                o0.x = v00; o0.y = v01;
                o1.x = v10; o1.y = v11;
                *(float2*)(C + (size_t)row0 * N + col)       = o0;
                *(float2*)(C + (size_t)(row0 + 8) * N + col) = o1;
            }
        }
    }
}

// ---------------------------------------------------------------------------
// Flash attention, tf32 MMA, cp.async double-buffered K/V, ldmatrix frags.
// qkv and y are tf32 bits. CTA = 128 q-rows of one (b,h).
// ---------------------------------------------------------------------------
#define LDQ 68
#define LDK 68
#define LDV 72
#define ATTN_SMEM (128 * LDQ + 2 * 64 * LDK + 2 * 64 * LDV)

__global__ __launch_bounds__(256) void attn_flash_mma(
    const unsigned* __restrict__ qkv, unsigned* __restrict__ y)
{
    extern __shared__ unsigned smu[];
    unsigned* sQ = smu;                      // [128][LDQ]; reused as P staging
    unsigned* sK = smu + 128 * LDQ;          // [2][64][LDK]
    unsigned* sV = sK + 2 * 64 * LDK;        // [2][64][LDV]

    const int qb   = blockIdx.x;
    const int h    = blockIdx.y;
    const int b    = blockIdx.z;
    const int tid  = threadIdx.x;
    const int wid  = tid >> 5;
    const int lane = tid & 31;
    const int g    = lane >> 2;
    const int t    = lane & 3;
    const int wq   = wid * 16;

    const size_t rs = 3 * CDIM;
    const size_t baseQ = ((size_t)(b * TSEQ + qb * 128)) * rs + h * DH;

    // ---- load Q tile [128][64] (already tf32) ----
#pragma unroll
    for (int it = 0; it < 8; it++) {
        int idx = it * 256 + tid;
        int r = idx >> 4, c = (idx & 15) << 2;
        *(uint4*)&sQ[r * LDQ + c] = *(const uint4*)(qkv + baseQ + (size_t)r * rs + c);
    }

    const int nkb = 2 * qb + 2;

    auto load_kv = [&](int buf, int kb) {
        const size_t baseK = ((size_t)(b * TSEQ + kb * 64)) * rs + CDIM + h * DH;
        unsigned* dK = sK + buf * 64 * LDK;
        unsigned* dV = sV + buf * 64 * LDV;
#pragma unroll
        for (int it = 0; it < 4; it++) {
            int idx = it * 256 + tid;
            int r = idx >> 4, c = (idx & 15) << 2;
            cp_async16(&dK[r * LDK + c], qkv + baseK + (size_t)r * rs + c);
            cp_async16(&dV[r * LDV + c], qkv + baseK + CDIM + (size_t)r * rs + c);
        }
        cp_commit();
    };

    load_kv(0, 0);
    __syncthreads();

    // ---- Q fragments into registers ----
    const int rowL   = lane & 15;
    const int colOff = (lane >> 4) << 2;
    unsigned qf[8][4];
#pragma unroll
    for (int kk = 0; kk < 8; kk++)
        ldm_x4(qf[kk], &sQ[(wq + rowL) * LDQ + kk * 8 + colOff]);

    unsigned* sP = sQ + wq * LDQ;   // per-warp P staging [16][LDQ]

    float o[8][4];
#pragma unroll
    for (int nt = 0; nt < 8; nt++)
#pragma unroll
        for (int j = 0; j < 4; j++) o[nt][j] = 0.f;
    float m0 = -1e30f, m1 = -1e30f, l0 = 0.f, l1 = 0.f;

    const int rowW = qb * 128 + wq;
    const int r0g  = rowW + g;
    const int r1g  = rowW + 8 + g;

    // K-frag ldmatrix.x2 lane address components
    const int rowK   = lane & 7;
    const int colKof = (lane & 8) ? 4 : 0;

    for (int kb = 0; kb < nkb; kb++) {
        if (kb + 1 < nkb) {
            load_kv((kb + 1) & 1, kb + 1);
            cp_wait1();
        } else {
            cp_wait0();
        }
        __syncthreads();

        const bool active = (rowW + 15 >= kb * 64);
        if (active) {
            const unsigned* cK = sK + (kb & 1) * 64 * LDK;
            const unsigned* cV = sV + (kb & 1) * 64 * LDV;

            // ---- S = Q @ K^T ----
            float s[8][4];
#pragma unroll
            for (int nt = 0; nt < 8; nt++)
#pragma unroll
                for (int j = 0; j < 4; j++) s[nt][j] = 0.f;

#pragma unroll
            for (int kk = 0; kk < 8; kk++) {
#pragma unroll
                for (int nt = 0; nt < 8; nt++) {
                    unsigned bf[2];
                    ldm_x2(bf, &cK[(nt * 8 + rowK) * LDK + kk * 8 + colKof]);
                    mma_tf32(s[nt], qf[kk], bf);
                }
            }

            // ---- scale + causal mask ----
            const float scale = 0.125f;
            if (kb * 64 + 63 > rowW) {
#pragma unroll
                for (int nt = 0; nt < 8; nt++) {
                    int c0 = kb * 64 + nt * 8 + 2 * t;
                    s[nt][0] = (c0     <= r0g) ? s[nt][0] * scale : -1e30f;
                    s[nt][1] = (c0 + 1 <= r0g) ? s[nt][1] * scale : -1e30f;
                    s[nt][2] = (c0     <= r1g) ? s[nt][2] * scale : -1e30f;
                    s[nt][3] = (c0 + 1 <= r1g) ? s[nt][3] * scale : -1e30f;
                }
            } else {
#pragma unroll
                for (int nt = 0; nt < 8; nt++)
#pragma unroll
                    for (int j = 0; j < 4; j++) s[nt][j] *= scale;
            }

            // ---- online softmax ----
            float mx0 = -1e30f, mx1 = -1e30f;
#pragma unroll
            for (int nt = 0; nt < 8; nt++) {
                mx0 = fmaxf(mx0, fmaxf(s[nt][0], s[nt][1]));
                mx1 = fmaxf(mx1, fmaxf(s[nt][2], s[nt][3]));
            }
            mx0 = fmaxf(mx0, __shfl_xor_sync(0xffffffffu, mx0, 1));
            mx0 = fmaxf(mx0, __shfl_xor_sync(0xffffffffu, mx0, 2));
            mx1 = fmaxf(mx1, __shfl_xor_sync(0xffffffffu, mx1, 1));
            mx1 = fmaxf(mx1, __shfl_xor_sync(0xffffffffu, mx1, 2));

            float mn0 = fmaxf(m0, mx0), mn1 = fmaxf(m1, mx1);
            float a0 = __expf(m0 - mn0), a1 = __expf(m1 - mn1);
            m0 = mn0; m1 = mn1;

            float sum0 = 0.f, sum1 = 0.f;
#pragma unroll
            for (int nt = 0; nt < 8; nt++) {
                s[nt][0] = __expf(s[nt][0] - mn0);
                s[nt][1] = __expf(s[nt][1] - mn0);
                s[nt][2] = __expf(s[nt][2] - mn1);
                s[nt][3] = __expf(s[nt][3] - mn1);
                sum0 += s[nt][0] + s[nt][1];
                sum1 += s[nt][2] + s[nt][3];
            }
            sum0 += __shfl_xor_sync(0xffffffffu, sum0, 1);
            sum0 += __shfl_xor_sync(0xffffffffu, sum0, 2);
            sum1 += __shfl_xor_sync(0xffffffffu, sum1, 1);
            sum1 += __shfl_xor_sync(0xffffffffu, sum1, 2);
            l0 = l0 * a0 + sum0;
            l1 = l1 * a1 + sum1;

#pragma unroll
            for (int nt = 0; nt < 8; nt++) {
                o[nt][0] *= a0; o[nt][1] *= a0;
                o[nt][2] *= a1; o[nt][3] *= a1;
            }

            // ---- stage P (tf32) into per-warp smem ----
            __syncwarp();
#pragma unroll
            for (int nt = 0; nt < 8; nt++) {
                int c0 = nt * 8 + 2 * t;
                uint2 u0, u1;
                u0.x = f2tf32(s[nt][0]); u0.y = f2tf32(s[nt][1]);
                u1.x = f2tf32(s[nt][2]); u1.y = f2tf32(s[nt][3]);
                *(uint2*)&sP[g * LDQ + c0]       = u0;
                *(uint2*)&sP[(8 + g) * LDQ + c0] = u1;
            }
            __syncwarp();

            // ---- O += P @ V ----
#pragma unroll
            for (int kk = 0; kk < 8; kk++) {
                unsigned pf[4];
                ldm_x4(pf, &sP[rowL * LDQ + kk * 8 + colOff]);
#pragma unroll
                for (int nt = 0; nt < 8; nt++) {
                    unsigned bf[2];
                    bf[0] = cV[(kk * 8 + t) * LDV + nt * 8 + g];
                    bf[1] = cV[(kk * 8 + t + 4) * LDV + nt * 8 + g];
                    mma_tf32(o[nt], pf, bf);
                }
            }
        }
        __syncthreads();
    }

    // ---- epilogue: normalize, write y (tf32 bits) ----
    float inv0 = 1.0f / l0, inv1 = 1.0f / l1;
    const size_t yr0 = ((size_t)(b * TSEQ) + r0g) * CDIM + h * DH;
    const size_t yr1 = ((size_t)(b * TSEQ) + r1g) * CDIM + h * DH;
#pragma unroll
    for (int nt = 0; nt < 8; nt++) {
        int c0 = nt * 8 + 2 * t;
        uint2 v0, v1;
        v0.x = f2tf32(o[nt][0] * inv0); v0.y = f2tf32(o[nt][1] * inv0);
        v1.x = f2tf32(o[nt][2] * inv1); v1.y = f2tf32(o[nt][3] * inv1);
        *(uint2*)(y + yr0 + c0) = v0;
        *(uint2*)(y + yr1 + c0) = v1;
    }
}

// ---------------------------------------------------------------------------
extern "C" void kernel_launch(void* const* d_in, const int* in_sizes, int n_in,
                              void* d_out, int out_size)
{
    const float* x      = (const float*)d_in[0];
    const float* w_attn = (const float*)d_in[1];
    const float* b_attn = (const float*)d_in[2];
    const float* w_proj = (const float*)d_in[3];
    const float* b_proj = (const float*)d_in[4];
    float* out = (float*)d_out;

    unsigned *x32, *wa32, *wp32, *qkv, *yb;
    cudaGetSymbolAddress((void**)&x32, g_x32);
    cudaGetSymbolAddress((void**)&wa32, g_wa32);
    cudaGetSymbolAddress((void**)&wp32, g_wp32);
    cudaGetSymbolAddress((void**)&qkv, g_qkv);
    cudaGetSymbolAddress((void**)&yb, g_y);

    const int smem_gemm = GEMM_SMEM * (int)sizeof(unsigned);   // 71680 B
    const int smem_attn = ATTN_SMEM * (int)sizeof(unsigned);   // 106496 B
    cudaFuncSetAttribute(gemm_tf32_bias<true>,
                         cudaFuncAttributeMaxDynamicSharedMemorySize, smem_gemm);
    cudaFuncSetAttribute(gemm_tf32_bias<false>,
                         cudaFuncAttributeMaxDynamicSharedMemorySize, smem_gemm);
    cudaFuncSetAttribute(attn_flash_mma,
                         cudaFuncAttributeMaxDynamicSharedMemorySize, smem_attn);

    const int M = BSZ * TSEQ;   // 4096

    // 0) pre-convert inputs to tf32
    const int nx  = M * CDIM / 4;             // 1,048,576
    const int nwa = CDIM * 3 * CDIM / 4;      //   786,432
    const int nwp = CDIM * CDIM / 4;          //   262,144
    cvt_tf32<<<(nx  + 255) / 256, 256>>>(x,      x32,  nx);
    cvt_tf32<<<(nwa + 255) / 256, 256>>>(w_attn, wa32, nwa);
    cvt_tf32<<<(nwp + 255) / 256, 256>>>(w_proj, wp32, nwp);

    // 1) qkv = x @ w_attn + b_attn     [4096, 3072]  (tf32 out)
    gemm_tf32_bias<true><<<dim3((3 * CDIM) / 128, M / 128), 256, smem_gemm>>>(
        x32, wa32, b_attn, qkv, M, 3 * CDIM, CDIM);

    // 2) flash attention -> y (tf32)   [4096, 1024]
    attn_flash_mma<<<dim3(TSEQ / 128, HN, BSZ), 256, smem_attn>>>(qkv, yb);

    // 3) out = y @ w_proj + b_proj     [4096, 1024]  (fp32 out)
    gemm_tf32_bias<false><<<dim3(CDIM / 128, M / 128), 256, smem_gemm>>>(
        yb, wp32, b_proj, out, M, CDIM, CDIM);
}